// round 15
// baseline (speedup 1.0000x reference)
#include <cuda_runtime.h>
#include <cuda_bf16.h>
#include <math.h>
#include <stdint.h>

#define Bn   16
#define Cn   512
#define HWn  576
#define CMn  (Cn*HWn)     // 294912
#define NTOT (Bn*HWn)     // 9216
#define NH   144          // 64-col half-tiles per row (9216/64)

// ---------------- device scratch (no allocs allowed) ----------------
__device__ __nv_bfloat16 g_qh[(size_t)NTOT*Cn];  // q, [n][c] bf16 transposed
__device__ __nv_bfloat16 g_kh[(size_t)NTOT*Cn];  // k, [n][c] bf16 transposed
__device__ float g_part[NTOT*NH];
__device__ float g_seeds[Bn*Cn];
__device__ float g_corr[NTOT];
__device__ float g_cormap[NTOT];
__device__ float g_proto[Cn];

__device__ __forceinline__ void cp16(uint32_t dst, const void* src) {
    asm volatile("cp.async.cg.shared.global [%0], [%1], 16;\n"
                 :: "r"(dst), "l"(src));
}
__device__ __forceinline__ uint32_t tf32r(float x) {
    uint32_t u;
    asm("cvt.rna.tf32.f32 %0, %1;" : "=r"(u) : "f"(x));
    return u;
}

// ---------------------------------------------------------------
// Tensor-core conv GEMM v2 (re-land of R13 under clock control):
// K=32 chunks, 3-stage ring, single barrier per chunk. Arithmetic
// bitwise-identical to the proven conv_tc.
// MODE 0: split tf32 (3 passes) + residual -> Yp fp32 (x5new).
// MODE 1/2: single tf32 pass -> g_qh / g_kh, bf16, transposed [n][c].
// ---------------------------------------------------------------
#define CKC   32
#define CLDW  36                        // floats per W smem row (32+4)
#define CLDX  136                       // floats per X smem row (128+8)
#define WSTG  (128 * CLDW)              // floats per W stage (4608)
#define XSTG  (CKC * CLDX)              // floats per X stage (4352)
#define CSMEM (3 * (WSTG + XSTG) * 4)   // 107520 B

template<int MODE>
__global__ void __launch_bounds__(256) conv_tc2(const float* __restrict__ Wm,
                                                const float* __restrict__ Xin,
                                                const float* __restrict__ bias,
                                                float* __restrict__ Yp)
{
    extern __shared__ __align__(16) float smf[];
    float* WsF = smf;               // 3 stages of [128][CLDW]
    float* XsF = smf + 3 * WSTG;    // 3 stages of [CKC][CLDX]

    const int t    = threadIdx.x;
    const int warp = t >> 5;
    const int lane = t & 31;
    const int wm   = (warp & 1) * 64;
    const int wn   = (warp >> 1) * 32;
    const int lr   = lane >> 2;
    const int lc   = lane & 3;
    const int N0   = blockIdx.x * 128;
    const int O0   = blockIdx.y * 128;

    uint32_t wo[4], xo[4];
    const float* wsp[4];
    const float* xsp[4];
    #pragma unroll
    for (int i = 0; i < 4; i++) {
        const int idx = t + i * 256;          // 0..1023
        const int wr = idx >> 3, wsg = idx & 7;
        wo[i]  = (uint32_t)(wr * CLDW + wsg * 4) * 4;
        wsp[i] = Wm + (size_t)(O0 + wr) * Cn + wsg * 4;
        const int xr = idx >> 5, xsg = idx & 31;
        const int col = N0 + xsg * 4;
        xo[i]  = (uint32_t)(xr * CLDX + xsg * 4) * 4;
        xsp[i] = Xin + (size_t)(col / HWn) * CMn + (size_t)xr * HWn + (col % HWn);
    }
    const uint32_t wB = (uint32_t)__cvta_generic_to_shared(WsF);
    const uint32_t xB = (uint32_t)__cvta_generic_to_shared(XsF);
    const uint32_t wStB = (uint32_t)(WSTG * 4);
    const uint32_t xStB = (uint32_t)(XSTG * 4);

    float d[4][4][4];
    #pragma unroll
    for (int mi = 0; mi < 4; mi++)
        #pragma unroll
        for (int ni = 0; ni < 4; ni++)
            #pragma unroll
            for (int r = 0; r < 4; r++) d[mi][ni][r] = 0.f;

    const int NCH = Cn / CKC;   // 16 chunks

    #pragma unroll
    for (int s = 0; s < 2; s++) {
        #pragma unroll
        for (int i = 0; i < 4; i++) {
            cp16(wB + s * wStB + wo[i], wsp[i] + s * CKC);
            cp16(xB + s * xStB + xo[i], xsp[i] + (size_t)s * CKC * HWn);
        }
        asm volatile("cp.async.commit_group;\n" ::: "memory");
    }

    for (int cc = 0; cc < NCH; cc++) {
        asm volatile("cp.async.wait_group 1;\n" ::: "memory");
        __syncthreads();
        if (cc + 2 < NCH) {
            const int j = cc + 2;
            const uint32_t ws = (j % 3) * wStB;
            const uint32_t xs = (j % 3) * xStB;
            #pragma unroll
            for (int i = 0; i < 4; i++) {
                cp16(wB + ws + wo[i], wsp[i] + j * CKC);
                cp16(xB + xs + xo[i], xsp[i] + (size_t)j * CKC * HWn);
            }
        }
        asm volatile("cp.async.commit_group;\n" ::: "memory");

        const float* Wst = WsF + (cc % 3) * WSTG;
        const float* Xst = XsF + (cc % 3) * XSTG;
        #pragma unroll
        for (int kf = 0; kf < 4; kf++) {
            const int k0 = kf * 8;
            uint32_t ah[4][4], al[4][4];
            #pragma unroll
            for (int mi = 0; mi < 4; mi++) {
                float f0 = Wst[(wm + mi * 16 + lr    ) * CLDW + k0 + lc    ];
                float f1 = Wst[(wm + mi * 16 + 8 + lr) * CLDW + k0 + lc    ];
                float f2 = Wst[(wm + mi * 16 + lr    ) * CLDW + k0 + lc + 4];
                float f3 = Wst[(wm + mi * 16 + 8 + lr) * CLDW + k0 + lc + 4];
                ah[mi][0] = tf32r(f0); ah[mi][1] = tf32r(f1);
                ah[mi][2] = tf32r(f2); ah[mi][3] = tf32r(f3);
                if (MODE == 0) {
                    al[mi][0] = tf32r(f0 - __uint_as_float(ah[mi][0]));
                    al[mi][1] = tf32r(f1 - __uint_as_float(ah[mi][1]));
                    al[mi][2] = tf32r(f2 - __uint_as_float(ah[mi][2]));
                    al[mi][3] = tf32r(f3 - __uint_as_float(ah[mi][3]));
                }
            }
            #pragma unroll
            for (int ni = 0; ni < 4; ni++) {
                float g0 = Xst[(k0 + lc    ) * CLDX + wn + ni * 8 + lr];
                float g1 = Xst[(k0 + lc + 4) * CLDX + wn + ni * 8 + lr];
                uint32_t bh0 = tf32r(g0), bh1 = tf32r(g1);
                uint32_t bl0 = 0, bl1 = 0;
                if (MODE == 0) {
                    bl0 = tf32r(g0 - __uint_as_float(bh0));
                    bl1 = tf32r(g1 - __uint_as_float(bh1));
                }
                #pragma unroll
                for (int mi = 0; mi < 4; mi++) {
                    asm volatile(
                        "mma.sync.aligned.m16n8k8.row.col.f32.tf32.tf32.f32 "
                        "{%0,%1,%2,%3}, {%4,%5,%6,%7}, {%8,%9}, {%0,%1,%2,%3};"
                        : "+f"(d[mi][ni][0]), "+f"(d[mi][ni][1]),
                          "+f"(d[mi][ni][2]), "+f"(d[mi][ni][3])
                        : "r"(ah[mi][0]), "r"(ah[mi][1]), "r"(ah[mi][2]), "r"(ah[mi][3]),
                          "r"(bh0), "r"(bh1));
                    if (MODE == 0) {
                        asm volatile(
                            "mma.sync.aligned.m16n8k8.row.col.f32.tf32.tf32.f32 "
                            "{%0,%1,%2,%3}, {%4,%5,%6,%7}, {%8,%9}, {%0,%1,%2,%3};"
                            : "+f"(d[mi][ni][0]), "+f"(d[mi][ni][1]),
                              "+f"(d[mi][ni][2]), "+f"(d[mi][ni][3])
                            : "r"(ah[mi][0]), "r"(ah[mi][1]), "r"(ah[mi][2]), "r"(ah[mi][3]),
                              "r"(bl0), "r"(bl1));
                        asm volatile(
                            "mma.sync.aligned.m16n8k8.row.col.f32.tf32.tf32.f32 "
                            "{%0,%1,%2,%3}, {%4,%5,%6,%7}, {%8,%9}, {%0,%1,%2,%3};"
                            : "+f"(d[mi][ni][0]), "+f"(d[mi][ni][1]),
                              "+f"(d[mi][ni][2]), "+f"(d[mi][ni][3])
                            : "r"(al[mi][0]), "r"(al[mi][1]), "r"(al[mi][2]), "r"(al[mi][3]),
                              "r"(bh0), "r"(bh1));
                    }
                }
            }
        }
        __syncthreads();
    }

    #pragma unroll
    for (int mi = 0; mi < 4; mi++) {
        const int row0 = O0 + wm + mi * 16 + lr;
        const float b0 = bias[row0];
        const float b1 = bias[row0 + 8];
        #pragma unroll
        for (int ni = 0; ni < 4; ni++) {
            const int col = N0 + wn + ni * 8 + 2 * lc;
            if (MODE == 0) {
                const int bb = col / HWn;
                const int m  = col - bb * HWn;
                float2 v0, v1;
                v0.x = d[mi][ni][0] + b0; v0.y = d[mi][ni][1] + b0;
                v1.x = d[mi][ni][2] + b1; v1.y = d[mi][ni][3] + b1;
                const float* x0 = Xin + (size_t)bb * CMn + (size_t)row0 * HWn + m;
                float2 r0 = *(const float2*)x0;
                float2 r1 = *(const float2*)(x0 + 8 * HWn);
                v0.x += r0.x; v0.y += r0.y;
                v1.x += r1.x; v1.y += r1.y;
                float* y0 = Yp + (size_t)bb * CMn + (size_t)row0 * HWn + m;
                *(float2*)y0 = v0;
                *(float2*)(y0 + 8 * HWn) = v1;
            } else {
                __nv_bfloat16* Yh = (MODE == 1) ? g_qh : g_kh;
                Yh[(size_t)col       * Cn + row0    ] = __float2bfloat16(d[mi][ni][0] + b0);
                Yh[(size_t)(col + 1) * Cn + row0    ] = __float2bfloat16(d[mi][ni][1] + b0);
                Yh[(size_t)col       * Cn + row0 + 8] = __float2bfloat16(d[mi][ni][2] + b1);
                Yh[(size_t)(col + 1) * Cn + row0 + 8] = __float2bfloat16(d[mi][ni][3] + b1);
            }
        }
    }
}

// ---------------------------------------------------------------
// bf16 scores GEMM v4 (R12/R14-proven, verbatim) — also the clock control.
// ---------------------------------------------------------------
#define KC4    64
#define LDQ4   72
#define TIL4   (128 * LDQ4 * 2)         // 18432 B per tile-stage
#define SMEMB4 (6 * TIL4)               // 110592 B

__global__ void __launch_bounds__(256) scores_bf4()
{
    extern __shared__ __align__(16) char sm[];
    __nv_bfloat16* Qb0 = (__nv_bfloat16*)sm;
    __nv_bfloat16* Kb0 = (__nv_bfloat16*)(sm + 3 * TIL4);
    float (*red)[4] = (float(*)[4])sm;

    const int t    = threadIdx.x;
    const int warp = t >> 5;
    const int lane = t & 31;
    const int wm   = (warp & 1) * 64;
    const int wn   = (warp >> 1) * 32;
    const int lr   = lane >> 2;
    const int lc   = lane & 3;
    const int R0   = blockIdx.x * 128;
    const int N0   = blockIdx.y * 128;

    uint32_t soff[4];
    const __nv_bfloat16* qsp[4];
    const __nv_bfloat16* ksp[4];
    #pragma unroll
    for (int i = 0; i < 4; i++) {
        const int idx = t + i * 256;
        const int row = idx >> 3;
        const int seg = idx & 7;
        soff[i] = row * (LDQ4 * 2) + seg * 16;
        qsp[i]  = g_qh + (size_t)(R0 + row) * Cn + seg * 8;
        ksp[i]  = g_kh + (size_t)(N0 + row) * Cn + seg * 8;
    }
    const uint32_t qB = (uint32_t)__cvta_generic_to_shared(Qb0);
    const uint32_t kB = (uint32_t)__cvta_generic_to_shared(Kb0);

    const int lrow = lane & 15;
    const int loff = (lane >> 4) * 16;
    const uint32_t qa0 = qB + (wm + lrow) * (LDQ4 * 2) + loff;
    const uint32_t ka0 = kB + (wn + lrow) * (LDQ4 * 2) + loff;

    float d[4][4][4];
    #pragma unroll
    for (int mi = 0; mi < 4; mi++)
        #pragma unroll
        for (int ni = 0; ni < 4; ni++)
            #pragma unroll
            for (int r = 0; r < 4; r++) d[mi][ni][r] = 0.f;

    const int NCH = Cn / KC4;

    #pragma unroll
    for (int s = 0; s < 2; s++) {
        #pragma unroll
        for (int i = 0; i < 4; i++) {
            cp16(qB + s * TIL4 + soff[i], qsp[i] + s * KC4);
            cp16(kB + s * TIL4 + soff[i], ksp[i] + s * KC4);
        }
        asm volatile("cp.async.commit_group;\n" ::: "memory");
    }

    #pragma unroll
    for (int cc = 0; cc < NCH; cc++) {
        asm volatile("cp.async.wait_group 1;\n" ::: "memory");
        __syncthreads();
        if (cc + 2 < NCH) {
            const uint32_t so = ((cc + 2) % 3) * TIL4;
            const int go = (cc + 2) * KC4;
            #pragma unroll
            for (int i = 0; i < 4; i++) {
                cp16(qB + so + soff[i], qsp[i] + go);
                cp16(kB + so + soff[i], ksp[i] + go);
            }
        }
        asm volatile("cp.async.commit_group;\n" ::: "memory");

        const uint32_t stO = (cc % 3) * TIL4;
        #pragma unroll
        for (int kf = 0; kf < 4; kf++) {
            const uint32_t ko = kf * 32;
            uint32_t a[4][4];
            #pragma unroll
            for (int mi = 0; mi < 4; mi++)
                asm volatile(
                    "ldmatrix.sync.aligned.m8n8.x4.shared.b16 {%0,%1,%2,%3}, [%4];"
                    : "=r"(a[mi][0]), "=r"(a[mi][1]), "=r"(a[mi][2]), "=r"(a[mi][3])
                    : "r"(qa0 + stO + ko + mi * 16 * (LDQ4 * 2)));
            uint32_t b[4][2];
            #pragma unroll
            for (int nj = 0; nj < 2; nj++)
                asm volatile(
                    "ldmatrix.sync.aligned.m8n8.x4.shared.b16 {%0,%1,%2,%3}, [%4];"
                    : "=r"(b[nj*2][0]), "=r"(b[nj*2+1][0]),
                      "=r"(b[nj*2][1]), "=r"(b[nj*2+1][1])
                    : "r"(ka0 + stO + ko + nj * 16 * (LDQ4 * 2)));
            #pragma unroll
            for (int mi = 0; mi < 4; mi++)
                #pragma unroll
                for (int ni = 0; ni < 4; ni++)
                    asm volatile(
                        "mma.sync.aligned.m16n8k16.row.col.f32.bf16.bf16.f32 "
                        "{%0,%1,%2,%3}, {%4,%5,%6,%7}, {%8,%9}, {%0,%1,%2,%3};"
                        : "+f"(d[mi][ni][0]), "+f"(d[mi][ni][1]),
                          "+f"(d[mi][ni][2]), "+f"(d[mi][ni][3])
                        : "r"(a[mi][0]), "r"(a[mi][1]), "r"(a[mi][2]), "r"(a[mi][3]),
                          "r"(b[ni][0]), "r"(b[ni][1]));
        }
    }
    __syncthreads();

    #pragma unroll
    for (int mi = 0; mi < 4; mi++) {
        float ra = -1e30f, rb = -1e30f;
        #pragma unroll
        for (int ni = 0; ni < 4; ni++) {
            ra = fmaxf(ra, fmaxf(d[mi][ni][0], d[mi][ni][1]));
            rb = fmaxf(rb, fmaxf(d[mi][ni][2], d[mi][ni][3]));
        }
        ra = fmaxf(ra, __shfl_xor_sync(0xFFFFFFFFu, ra, 1));
        ra = fmaxf(ra, __shfl_xor_sync(0xFFFFFFFFu, ra, 2));
        rb = fmaxf(rb, __shfl_xor_sync(0xFFFFFFFFu, rb, 1));
        rb = fmaxf(rb, __shfl_xor_sync(0xFFFFFFFFu, rb, 2));
        if (lc == 0) {
            red[wm + mi * 16 + lr    ][warp >> 1] = ra;
            red[wm + mi * 16 + 8 + lr][warp >> 1] = rb;
        }
    }
    __syncthreads();

    if (t < 128) {
        const float h0 = fmaxf(red[t][0], red[t][1]);
        const float h1 = fmaxf(red[t][2], red[t][3]);
        const size_t r2 = R0 + t;
        g_part[r2 * NH + blockIdx.y * 2    ] = h0;
        g_part[r2 * NH + blockIdx.y * 2 + 1] = h1;
    }
}

// ---------------------------------------------------------------
__global__ void xw_mask_kernel(float* __restrict__ o_mask)
{
    __shared__ float smax[HWn];
    const int b = blockIdx.x, p = threadIdx.x;
    const float* gp = g_part + (size_t)(b * HWn + p) * NH;
    float s = 0.f;
    #pragma unroll
    for (int bk = 0; bk < Bn; bk++) {
        float m = gp[bk * 9];
        #pragma unroll
        for (int h = 1; h < 9; h++) m = fmaxf(m, gp[bk * 9 + h]);
        s += m;
    }
    smax[p] = s;
    __syncthreads();
    for (int st = 512; st > 0; st >>= 1) {
        if (p < st && p + st < HWn) smax[p] = fmaxf(smax[p], smax[p + st]);
        __syncthreads();
    }
    o_mask[b * HWn + p] = (s == smax[0]) ? 1.0f : 0.0f;
}

__global__ void seeds_kernel(const float* __restrict__ x5n,
                             const float* __restrict__ mask)
{
    __shared__ int cnt;
    __shared__ int plist[HWn];
    __shared__ float red[512];
    const int b = blockIdx.x, c = threadIdx.x;
    if (c == 0) cnt = 0;
    __syncthreads();
    for (int p = c; p < HWn; p += 512)
        if (mask[b * HWn + p] > 0.5f) {
            int i = atomicAdd(&cnt, 1);
            plist[i] = p;
        }
    __syncthreads();
    float s = 0.f;
    const int n = cnt;
    for (int i = 0; i < n; i++) {
        const int p = plist[i];
        const float x = x5n[(size_t)b * CMn + (size_t)c * HWn + p];
        red[c] = x * x;
        __syncthreads();
        for (int st = 256; st > 0; st >>= 1) {
            if (c < st) red[c] += red[c + st];
            __syncthreads();
        }
        const float invn = 1.0f / fmaxf(sqrtf(red[0]), 1e-12f);
        s += x * invn;
        __syncthreads();
    }
    g_seeds[b * Cn + c] = s;
}

__global__ void __launch_bounds__(64) corr_k(const float* __restrict__ x5n)
{
    __shared__ __align__(16) float ssT[Cn][Bn];
    const int b = blockIdx.x;
    const int p = blockIdx.y * 64 + threadIdx.x;
    for (int i = threadIdx.x; i < Cn * Bn; i += 64) {
        int c = i >> 4, s = i & 15;
        ssT[c][s] = g_seeds[s * Cn + c];
    }
    __syncthreads();
    float acc[Bn] = {};
    float sq = 0.f;
    const float* xp = x5n + (size_t)b * CMn + p;
    for (int c = 0; c < Cn; c++) {
        const float x = xp[(size_t)c * HWn];
        sq += x * x;
        #pragma unroll
        for (int s4 = 0; s4 < 4; s4++) {
            float4 sv = *(const float4*)&ssT[c][s4 * 4];
            acc[s4 * 4 + 0] += x * sv.x;
            acc[s4 * 4 + 1] += x * sv.y;
            acc[s4 * 4 + 2] += x * sv.z;
            acc[s4 * 4 + 3] += x * sv.w;
        }
    }
    const float invn = 1.0f / fmaxf(sqrtf(sq), 1e-12f);
    float r = 0.f;
    #pragma unroll
    for (int s = 0; s < Bn; s++) r += fmaxf(acc[s], 0.f);
    g_corr[b * HWn + p] = r * invn * (1.0f / Bn);
}

__global__ void cormap_k()
{
    __shared__ float smn[HWn], smx[HWn];
    const int b = blockIdx.x, p = threadIdx.x;
    const float v = g_corr[b * HWn + p];
    smn[p] = v; smx[p] = v;
    __syncthreads();
    for (int st = 512; st > 0; st >>= 1) {
        if (p < st && p + st < HWn) {
            smn[p] = fminf(smn[p], smn[p + st]);
            smx[p] = fmaxf(smx[p], smx[p + st]);
        }
        __syncthreads();
    }
    g_cormap[b * HWn + p] = (v - smn[0]) / (smx[0] - smn[0] + 1e-12f);
}

__global__ void proto_kernel(const float* __restrict__ x5n,
                             float* __restrict__ o_pro)
{
    __shared__ float sred[256];
    const int c = blockIdx.x, t = threadIdx.x;
    float s = 0.f;
    for (int n = t; n < NTOT; n += 256) {
        int b = n / HWn, p = n - b * HWn;
        s += x5n[(size_t)b * CMn + (size_t)c * HWn + p] * g_cormap[n];
    }
    sred[t] = s;
    __syncthreads();
    for (int st = 128; st > 0; st >>= 1) {
        if (t < st) sred[t] += sred[t + st];
        __syncthreads();
    }
    if (t == 0) {
        float v = sred[0] * (1.0f / NTOT);
        g_proto[c] = v;
        o_pro[c] = v;
    }
}

__global__ void out3_kernel(const float* __restrict__ x5n,
                            float* __restrict__ o3)
{
    const int i = blockIdx.x * 256 + threadIdx.x;
    const int b = i / CMn;
    const int r = i - b * CMn;
    const int c = r / HWn;
    const int p = r - c * HWn;
    o3[i] = x5n[i] * (g_proto[c] + g_cormap[b * HWn + p]);
}

// ---------------------------------------------------------------
extern "C" void kernel_launch(void* const* d_in, const int* in_sizes, int n_in,
                              void* d_out, int out_size)
{
    const float* x5    = (const float*)d_in[0];
    const float* convw = (const float*)d_in[1];
    const float* convb = (const float*)d_in[2];
    const float* qw    = (const float*)d_in[3];
    const float* qb    = (const float*)d_in[4];
    const float* kw    = (const float*)d_in[5];
    const float* kb    = (const float*)d_in[6];

    float* out    = (float*)d_out;
    float* o_x5   = out;
    float* o_pro  = out + (size_t)Bn * CMn;
    float* o_3    = o_pro + Cn;
    float* o_mask = o_3 + (size_t)Bn * CMn;

    static bool attr_set = false;
    if (!attr_set) {
        cudaFuncSetAttribute(scores_bf4,
                             cudaFuncAttributeMaxDynamicSharedMemorySize, SMEMB4);
        cudaFuncSetAttribute(conv_tc2<0>,
                             cudaFuncAttributeMaxDynamicSharedMemorySize, CSMEM);
        cudaFuncSetAttribute(conv_tc2<1>,
                             cudaFuncAttributeMaxDynamicSharedMemorySize, CSMEM);
        cudaFuncSetAttribute(conv_tc2<2>,
                             cudaFuncAttributeMaxDynamicSharedMemorySize, CSMEM);
        attr_set = true;
    }

    dim3 cgrid(NTOT / 128, Cn / 128);

    conv_tc2<0><<<cgrid, 256, CSMEM>>>(convw, x5,   convb, o_x5);
    conv_tc2<1><<<cgrid, 256, CSMEM>>>(qw,    o_x5, qb,    nullptr);
    conv_tc2<2><<<cgrid, 256, CSMEM>>>(kw,    o_x5, kb,    nullptr);

    scores_bf4<<<dim3(NTOT / 128, NTOT / 128), 256, SMEMB4>>>();

    xw_mask_kernel<<<Bn, HWn>>>(o_mask);
    seeds_kernel<<<Bn, Cn>>>(o_x5, o_mask);
    corr_k<<<dim3(Bn, 9), 64>>>(o_x5);
    cormap_k<<<Bn, HWn>>>();
    proto_kernel<<<Cn, 256>>>(o_x5, o_pro);
    out3_kernel<<<(Bn * CMn) / 256, 256>>>(o_x5, o_3);
}

// round 16
// speedup vs baseline: 1.1060x; 1.1060x over previous
#include <cuda_runtime.h>
#include <cuda_bf16.h>
#include <math.h>
#include <stdint.h>

#define Bn   16
#define Cn   512
#define HWn  576
#define CMn  (Cn*HWn)     // 294912
#define NTOT (Bn*HWn)     // 9216
#define NH   144          // 64-col half-tiles per row (9216/64)

// ---------------- device scratch (no allocs allowed) ----------------
__device__ __nv_bfloat16 g_qh[(size_t)NTOT*Cn];  // q, [n][c] bf16 transposed
__device__ __nv_bfloat16 g_kh[(size_t)NTOT*Cn];  // k, [n][c] bf16 transposed
__device__ float g_part[NTOT*NH];
__device__ float g_seeds[Bn*Cn];
__device__ float g_corr[NTOT];
__device__ float g_cormap[NTOT];
__device__ float g_proto[Cn];

__device__ __forceinline__ void cp16(uint32_t dst, const void* src) {
    asm volatile("cp.async.cg.shared.global [%0], [%1], 16;\n"
                 :: "r"(dst), "l"(src));
}
__device__ __forceinline__ uint32_t tf32r(float x) {
    uint32_t u;
    asm("cvt.rna.tf32.f32 %0, %1;" : "=r"(u) : "f"(x));
    return u;
}

// ---------------------------------------------------------------
// Tensor-core conv GEMM: K=32 chunks, 3-stage ring, single barrier
// per chunk. SINGLE-PASS tf32 for all modes (error budget analysis:
// conv term std 0.45 vs residual 1.0 -> x5new rel_err ~1.4e-4,
// 7x under threshold; q/k score perturbation ~0.015%, mask-safe).
// MODE 0: + residual -> Yp fp32 (x5new).
// MODE 1/2: -> g_qh / g_kh, bf16, transposed [n][c].
// ---------------------------------------------------------------
#define CKC   32
#define CLDW  36                        // floats per W smem row (32+4)
#define CLDX  136                       // floats per X smem row (128+8)
#define WSTG  (128 * CLDW)              // floats per W stage (4608)
#define XSTG  (CKC * CLDX)              // floats per X stage (4352)
#define CSMEM (3 * (WSTG + XSTG) * 4)   // 107520 B

template<int MODE>
__global__ void __launch_bounds__(256) conv_tc2(const float* __restrict__ Wm,
                                                const float* __restrict__ Xin,
                                                const float* __restrict__ bias,
                                                float* __restrict__ Yp)
{
    extern __shared__ __align__(16) float smf[];
    float* WsF = smf;               // 3 stages of [128][CLDW]
    float* XsF = smf + 3 * WSTG;    // 3 stages of [CKC][CLDX]

    const int t    = threadIdx.x;
    const int warp = t >> 5;
    const int lane = t & 31;
    const int wm   = (warp & 1) * 64;
    const int wn   = (warp >> 1) * 32;
    const int lr   = lane >> 2;
    const int lc   = lane & 3;
    const int N0   = blockIdx.x * 128;
    const int O0   = blockIdx.y * 128;

    uint32_t wo[4], xo[4];
    const float* wsp[4];
    const float* xsp[4];
    #pragma unroll
    for (int i = 0; i < 4; i++) {
        const int idx = t + i * 256;          // 0..1023
        const int wr = idx >> 3, wsg = idx & 7;
        wo[i]  = (uint32_t)(wr * CLDW + wsg * 4) * 4;
        wsp[i] = Wm + (size_t)(O0 + wr) * Cn + wsg * 4;
        const int xr = idx >> 5, xsg = idx & 31;
        const int col = N0 + xsg * 4;
        xo[i]  = (uint32_t)(xr * CLDX + xsg * 4) * 4;
        xsp[i] = Xin + (size_t)(col / HWn) * CMn + (size_t)xr * HWn + (col % HWn);
    }
    const uint32_t wB = (uint32_t)__cvta_generic_to_shared(WsF);
    const uint32_t xB = (uint32_t)__cvta_generic_to_shared(XsF);
    const uint32_t wStB = (uint32_t)(WSTG * 4);
    const uint32_t xStB = (uint32_t)(XSTG * 4);

    float d[4][4][4];
    #pragma unroll
    for (int mi = 0; mi < 4; mi++)
        #pragma unroll
        for (int ni = 0; ni < 4; ni++)
            #pragma unroll
            for (int r = 0; r < 4; r++) d[mi][ni][r] = 0.f;

    const int NCH = Cn / CKC;   // 16 chunks

    #pragma unroll
    for (int s = 0; s < 2; s++) {
        #pragma unroll
        for (int i = 0; i < 4; i++) {
            cp16(wB + s * wStB + wo[i], wsp[i] + s * CKC);
            cp16(xB + s * xStB + xo[i], xsp[i] + (size_t)s * CKC * HWn);
        }
        asm volatile("cp.async.commit_group;\n" ::: "memory");
    }

    for (int cc = 0; cc < NCH; cc++) {
        asm volatile("cp.async.wait_group 1;\n" ::: "memory");
        __syncthreads();
        if (cc + 2 < NCH) {
            const int j = cc + 2;
            const uint32_t ws = (j % 3) * wStB;
            const uint32_t xs = (j % 3) * xStB;
            #pragma unroll
            for (int i = 0; i < 4; i++) {
                cp16(wB + ws + wo[i], wsp[i] + j * CKC);
                cp16(xB + xs + xo[i], xsp[i] + (size_t)j * CKC * HWn);
            }
        }
        asm volatile("cp.async.commit_group;\n" ::: "memory");

        const float* Wst = WsF + (cc % 3) * WSTG;
        const float* Xst = XsF + (cc % 3) * XSTG;
        #pragma unroll
        for (int kf = 0; kf < 4; kf++) {
            const int k0 = kf * 8;
            uint32_t ah[4][4];
            #pragma unroll
            for (int mi = 0; mi < 4; mi++) {
                ah[mi][0] = tf32r(Wst[(wm + mi * 16 + lr    ) * CLDW + k0 + lc    ]);
                ah[mi][1] = tf32r(Wst[(wm + mi * 16 + 8 + lr) * CLDW + k0 + lc    ]);
                ah[mi][2] = tf32r(Wst[(wm + mi * 16 + lr    ) * CLDW + k0 + lc + 4]);
                ah[mi][3] = tf32r(Wst[(wm + mi * 16 + 8 + lr) * CLDW + k0 + lc + 4]);
            }
            #pragma unroll
            for (int ni = 0; ni < 4; ni++) {
                uint32_t bh0 = tf32r(Xst[(k0 + lc    ) * CLDX + wn + ni * 8 + lr]);
                uint32_t bh1 = tf32r(Xst[(k0 + lc + 4) * CLDX + wn + ni * 8 + lr]);
                #pragma unroll
                for (int mi = 0; mi < 4; mi++)
                    asm volatile(
                        "mma.sync.aligned.m16n8k8.row.col.f32.tf32.tf32.f32 "
                        "{%0,%1,%2,%3}, {%4,%5,%6,%7}, {%8,%9}, {%0,%1,%2,%3};"
                        : "+f"(d[mi][ni][0]), "+f"(d[mi][ni][1]),
                          "+f"(d[mi][ni][2]), "+f"(d[mi][ni][3])
                        : "r"(ah[mi][0]), "r"(ah[mi][1]), "r"(ah[mi][2]), "r"(ah[mi][3]),
                          "r"(bh0), "r"(bh1));
            }
        }
        __syncthreads();
    }

    #pragma unroll
    for (int mi = 0; mi < 4; mi++) {
        const int row0 = O0 + wm + mi * 16 + lr;
        const float b0 = bias[row0];
        const float b1 = bias[row0 + 8];
        #pragma unroll
        for (int ni = 0; ni < 4; ni++) {
            const int col = N0 + wn + ni * 8 + 2 * lc;
            if (MODE == 0) {
                const int bb = col / HWn;
                const int m  = col - bb * HWn;
                float2 v0, v1;
                v0.x = d[mi][ni][0] + b0; v0.y = d[mi][ni][1] + b0;
                v1.x = d[mi][ni][2] + b1; v1.y = d[mi][ni][3] + b1;
                const float* x0 = Xin + (size_t)bb * CMn + (size_t)row0 * HWn + m;
                float2 r0 = *(const float2*)x0;
                float2 r1 = *(const float2*)(x0 + 8 * HWn);
                v0.x += r0.x; v0.y += r0.y;
                v1.x += r1.x; v1.y += r1.y;
                float* y0 = Yp + (size_t)bb * CMn + (size_t)row0 * HWn + m;
                *(float2*)y0 = v0;
                *(float2*)(y0 + 8 * HWn) = v1;
            } else {
                __nv_bfloat16* Yh = (MODE == 1) ? g_qh : g_kh;
                Yh[(size_t)col       * Cn + row0    ] = __float2bfloat16(d[mi][ni][0] + b0);
                Yh[(size_t)(col + 1) * Cn + row0    ] = __float2bfloat16(d[mi][ni][1] + b0);
                Yh[(size_t)col       * Cn + row0 + 8] = __float2bfloat16(d[mi][ni][2] + b1);
                Yh[(size_t)(col + 1) * Cn + row0 + 8] = __float2bfloat16(d[mi][ni][3] + b1);
            }
        }
    }
}

// ---------------------------------------------------------------
// bf16 scores GEMM v4 (R12/R14/R15-proven, verbatim) — clock control.
// ---------------------------------------------------------------
#define KC4    64
#define LDQ4   72
#define TIL4   (128 * LDQ4 * 2)         // 18432 B per tile-stage
#define SMEMB4 (6 * TIL4)               // 110592 B

__global__ void __launch_bounds__(256) scores_bf4()
{
    extern __shared__ __align__(16) char sm[];
    __nv_bfloat16* Qb0 = (__nv_bfloat16*)sm;
    __nv_bfloat16* Kb0 = (__nv_bfloat16*)(sm + 3 * TIL4);
    float (*red)[4] = (float(*)[4])sm;

    const int t    = threadIdx.x;
    const int warp = t >> 5;
    const int lane = t & 31;
    const int wm   = (warp & 1) * 64;
    const int wn   = (warp >> 1) * 32;
    const int lr   = lane >> 2;
    const int lc   = lane & 3;
    const int R0   = blockIdx.x * 128;
    const int N0   = blockIdx.y * 128;

    uint32_t soff[4];
    const __nv_bfloat16* qsp[4];
    const __nv_bfloat16* ksp[4];
    #pragma unroll
    for (int i = 0; i < 4; i++) {
        const int idx = t + i * 256;
        const int row = idx >> 3;
        const int seg = idx & 7;
        soff[i] = row * (LDQ4 * 2) + seg * 16;
        qsp[i]  = g_qh + (size_t)(R0 + row) * Cn + seg * 8;
        ksp[i]  = g_kh + (size_t)(N0 + row) * Cn + seg * 8;
    }
    const uint32_t qB = (uint32_t)__cvta_generic_to_shared(Qb0);
    const uint32_t kB = (uint32_t)__cvta_generic_to_shared(Kb0);

    const int lrow = lane & 15;
    const int loff = (lane >> 4) * 16;
    const uint32_t qa0 = qB + (wm + lrow) * (LDQ4 * 2) + loff;
    const uint32_t ka0 = kB + (wn + lrow) * (LDQ4 * 2) + loff;

    float d[4][4][4];
    #pragma unroll
    for (int mi = 0; mi < 4; mi++)
        #pragma unroll
        for (int ni = 0; ni < 4; ni++)
            #pragma unroll
            for (int r = 0; r < 4; r++) d[mi][ni][r] = 0.f;

    const int NCH = Cn / KC4;

    #pragma unroll
    for (int s = 0; s < 2; s++) {
        #pragma unroll
        for (int i = 0; i < 4; i++) {
            cp16(qB + s * TIL4 + soff[i], qsp[i] + s * KC4);
            cp16(kB + s * TIL4 + soff[i], ksp[i] + s * KC4);
        }
        asm volatile("cp.async.commit_group;\n" ::: "memory");
    }

    #pragma unroll
    for (int cc = 0; cc < NCH; cc++) {
        asm volatile("cp.async.wait_group 1;\n" ::: "memory");
        __syncthreads();
        if (cc + 2 < NCH) {
            const uint32_t so = ((cc + 2) % 3) * TIL4;
            const int go = (cc + 2) * KC4;
            #pragma unroll
            for (int i = 0; i < 4; i++) {
                cp16(qB + so + soff[i], qsp[i] + go);
                cp16(kB + so + soff[i], ksp[i] + go);
            }
        }
        asm volatile("cp.async.commit_group;\n" ::: "memory");

        const uint32_t stO = (cc % 3) * TIL4;
        #pragma unroll
        for (int kf = 0; kf < 4; kf++) {
            const uint32_t ko = kf * 32;
            uint32_t a[4][4];
            #pragma unroll
            for (int mi = 0; mi < 4; mi++)
                asm volatile(
                    "ldmatrix.sync.aligned.m8n8.x4.shared.b16 {%0,%1,%2,%3}, [%4];"
                    : "=r"(a[mi][0]), "=r"(a[mi][1]), "=r"(a[mi][2]), "=r"(a[mi][3])
                    : "r"(qa0 + stO + ko + mi * 16 * (LDQ4 * 2)));
            uint32_t b[4][2];
            #pragma unroll
            for (int nj = 0; nj < 2; nj++)
                asm volatile(
                    "ldmatrix.sync.aligned.m8n8.x4.shared.b16 {%0,%1,%2,%3}, [%4];"
                    : "=r"(b[nj*2][0]), "=r"(b[nj*2+1][0]),
                      "=r"(b[nj*2][1]), "=r"(b[nj*2+1][1])
                    : "r"(ka0 + stO + ko + nj * 16 * (LDQ4 * 2)));
            #pragma unroll
            for (int mi = 0; mi < 4; mi++)
                #pragma unroll
                for (int ni = 0; ni < 4; ni++)
                    asm volatile(
                        "mma.sync.aligned.m16n8k16.row.col.f32.bf16.bf16.f32 "
                        "{%0,%1,%2,%3}, {%4,%5,%6,%7}, {%8,%9}, {%0,%1,%2,%3};"
                        : "+f"(d[mi][ni][0]), "+f"(d[mi][ni][1]),
                          "+f"(d[mi][ni][2]), "+f"(d[mi][ni][3])
                        : "r"(a[mi][0]), "r"(a[mi][1]), "r"(a[mi][2]), "r"(a[mi][3]),
                          "r"(b[ni][0]), "r"(b[ni][1]));
        }
    }
    __syncthreads();

    #pragma unroll
    for (int mi = 0; mi < 4; mi++) {
        float ra = -1e30f, rb = -1e30f;
        #pragma unroll
        for (int ni = 0; ni < 4; ni++) {
            ra = fmaxf(ra, fmaxf(d[mi][ni][0], d[mi][ni][1]));
            rb = fmaxf(rb, fmaxf(d[mi][ni][2], d[mi][ni][3]));
        }
        ra = fmaxf(ra, __shfl_xor_sync(0xFFFFFFFFu, ra, 1));
        ra = fmaxf(ra, __shfl_xor_sync(0xFFFFFFFFu, ra, 2));
        rb = fmaxf(rb, __shfl_xor_sync(0xFFFFFFFFu, rb, 1));
        rb = fmaxf(rb, __shfl_xor_sync(0xFFFFFFFFu, rb, 2));
        if (lc == 0) {
            red[wm + mi * 16 + lr    ][warp >> 1] = ra;
            red[wm + mi * 16 + 8 + lr][warp >> 1] = rb;
        }
    }
    __syncthreads();

    if (t < 128) {
        const float h0 = fmaxf(red[t][0], red[t][1]);
        const float h1 = fmaxf(red[t][2], red[t][3]);
        const size_t r2 = R0 + t;
        g_part[r2 * NH + blockIdx.y * 2    ] = h0;
        g_part[r2 * NH + blockIdx.y * 2 + 1] = h1;
    }
}

// ---------------------------------------------------------------
__global__ void xw_mask_kernel(float* __restrict__ o_mask)
{
    __shared__ float smax[HWn];
    const int b = blockIdx.x, p = threadIdx.x;
    const float* gp = g_part + (size_t)(b * HWn + p) * NH;
    float s = 0.f;
    #pragma unroll
    for (int bk = 0; bk < Bn; bk++) {
        float m = gp[bk * 9];
        #pragma unroll
        for (int h = 1; h < 9; h++) m = fmaxf(m, gp[bk * 9 + h]);
        s += m;
    }
    smax[p] = s;
    __syncthreads();
    for (int st = 512; st > 0; st >>= 1) {
        if (p < st && p + st < HWn) smax[p] = fmaxf(smax[p], smax[p + st]);
        __syncthreads();
    }
    o_mask[b * HWn + p] = (s == smax[0]) ? 1.0f : 0.0f;
}

__global__ void seeds_kernel(const float* __restrict__ x5n,
                             const float* __restrict__ mask)
{
    __shared__ int cnt;
    __shared__ int plist[HWn];
    __shared__ float red[512];
    const int b = blockIdx.x, c = threadIdx.x;
    if (c == 0) cnt = 0;
    __syncthreads();
    for (int p = c; p < HWn; p += 512)
        if (mask[b * HWn + p] > 0.5f) {
            int i = atomicAdd(&cnt, 1);
            plist[i] = p;
        }
    __syncthreads();
    float s = 0.f;
    const int n = cnt;
    for (int i = 0; i < n; i++) {
        const int p = plist[i];
        const float x = x5n[(size_t)b * CMn + (size_t)c * HWn + p];
        red[c] = x * x;
        __syncthreads();
        for (int st = 256; st > 0; st >>= 1) {
            if (c < st) red[c] += red[c + st];
            __syncthreads();
        }
        const float invn = 1.0f / fmaxf(sqrtf(red[0]), 1e-12f);
        s += x * invn;
        __syncthreads();
    }
    g_seeds[b * Cn + c] = s;
}

__global__ void __launch_bounds__(64) corr_k(const float* __restrict__ x5n)
{
    __shared__ __align__(16) float ssT[Cn][Bn];
    const int b = blockIdx.x;
    const int p = blockIdx.y * 64 + threadIdx.x;
    for (int i = threadIdx.x; i < Cn * Bn; i += 64) {
        int c = i >> 4, s = i & 15;
        ssT[c][s] = g_seeds[s * Cn + c];
    }
    __syncthreads();
    float acc[Bn] = {};
    float sq = 0.f;
    const float* xp = x5n + (size_t)b * CMn + p;
    for (int c = 0; c < Cn; c++) {
        const float x = xp[(size_t)c * HWn];
        sq += x * x;
        #pragma unroll
        for (int s4 = 0; s4 < 4; s4++) {
            float4 sv = *(const float4*)&ssT[c][s4 * 4];
            acc[s4 * 4 + 0] += x * sv.x;
            acc[s4 * 4 + 1] += x * sv.y;
            acc[s4 * 4 + 2] += x * sv.z;
            acc[s4 * 4 + 3] += x * sv.w;
        }
    }
    const float invn = 1.0f / fmaxf(sqrtf(sq), 1e-12f);
    float r = 0.f;
    #pragma unroll
    for (int s = 0; s < Bn; s++) r += fmaxf(acc[s], 0.f);
    g_corr[b * HWn + p] = r * invn * (1.0f / Bn);
}

__global__ void cormap_k()
{
    __shared__ float smn[HWn], smx[HWn];
    const int b = blockIdx.x, p = threadIdx.x;
    const float v = g_corr[b * HWn + p];
    smn[p] = v; smx[p] = v;
    __syncthreads();
    for (int st = 512; st > 0; st >>= 1) {
        if (p < st && p + st < HWn) {
            smn[p] = fminf(smn[p], smn[p + st]);
            smx[p] = fmaxf(smx[p], smx[p + st]);
        }
        __syncthreads();
    }
    g_cormap[b * HWn + p] = (v - smn[0]) / (smx[0] - smn[0] + 1e-12f);
}

__global__ void proto_kernel(const float* __restrict__ x5n,
                             float* __restrict__ o_pro)
{
    __shared__ float sred[256];
    const int c = blockIdx.x, t = threadIdx.x;
    float s = 0.f;
    for (int n = t; n < NTOT; n += 256) {
        int b = n / HWn, p = n - b * HWn;
        s += x5n[(size_t)b * CMn + (size_t)c * HWn + p] * g_cormap[n];
    }
    sred[t] = s;
    __syncthreads();
    for (int st = 128; st > 0; st >>= 1) {
        if (t < st) sred[t] += sred[t + st];
        __syncthreads();
    }
    if (t == 0) {
        float v = sred[0] * (1.0f / NTOT);
        g_proto[c] = v;
        o_pro[c] = v;
    }
}

__global__ void out3_kernel(const float* __restrict__ x5n,
                            float* __restrict__ o3)
{
    const int i = blockIdx.x * 256 + threadIdx.x;
    const int b = i / CMn;
    const int r = i - b * CMn;
    const int c = r / HWn;
    const int p = r - c * HWn;
    o3[i] = x5n[i] * (g_proto[c] + g_cormap[b * HWn + p]);
}

// ---------------------------------------------------------------
extern "C" void kernel_launch(void* const* d_in, const int* in_sizes, int n_in,
                              void* d_out, int out_size)
{
    const float* x5    = (const float*)d_in[0];
    const float* convw = (const float*)d_in[1];
    const float* convb = (const float*)d_in[2];
    const float* qw    = (const float*)d_in[3];
    const float* qb    = (const float*)d_in[4];
    const float* kw    = (const float*)d_in[5];
    const float* kb    = (const float*)d_in[6];

    float* out    = (float*)d_out;
    float* o_x5   = out;
    float* o_pro  = out + (size_t)Bn * CMn;
    float* o_3    = o_pro + Cn;
    float* o_mask = o_3 + (size_t)Bn * CMn;

    static bool attr_set = false;
    if (!attr_set) {
        cudaFuncSetAttribute(scores_bf4,
                             cudaFuncAttributeMaxDynamicSharedMemorySize, SMEMB4);
        cudaFuncSetAttribute(conv_tc2<0>,
                             cudaFuncAttributeMaxDynamicSharedMemorySize, CSMEM);
        cudaFuncSetAttribute(conv_tc2<1>,
                             cudaFuncAttributeMaxDynamicSharedMemorySize, CSMEM);
        cudaFuncSetAttribute(conv_tc2<2>,
                             cudaFuncAttributeMaxDynamicSharedMemorySize, CSMEM);
        attr_set = true;
    }

    dim3 cgrid(NTOT / 128, Cn / 128);

    conv_tc2<0><<<cgrid, 256, CSMEM>>>(convw, x5,   convb, o_x5);
    conv_tc2<1><<<cgrid, 256, CSMEM>>>(qw,    o_x5, qb,    nullptr);
    conv_tc2<2><<<cgrid, 256, CSMEM>>>(kw,    o_x5, kb,    nullptr);

    scores_bf4<<<dim3(NTOT / 128, NTOT / 128), 256, SMEMB4>>>();

    xw_mask_kernel<<<Bn, HWn>>>(o_mask);
    seeds_kernel<<<Bn, Cn>>>(o_x5, o_mask);
    corr_k<<<dim3(Bn, 9), 64>>>(o_x5);
    cormap_k<<<Bn, HWn>>>();
    proto_kernel<<<Cn, 256>>>(o_x5, o_pro);
    out3_kernel<<<(Bn * CMn) / 256, 256>>>(o_x5, o_3);
}

// round 17
// speedup vs baseline: 1.1349x; 1.0261x over previous
#include <cuda_runtime.h>
#include <cuda_bf16.h>
#include <math.h>
#include <stdint.h>

#define Bn   16
#define Cn   512
#define HWn  576
#define CMn  (Cn*HWn)     // 294912
#define NTOT (Bn*HWn)     // 9216
#define NH   144          // 64-col half-tiles per row (9216/64)

// ---------------- device scratch (no allocs allowed) ----------------
__device__ __nv_bfloat16 g_qh[(size_t)NTOT*Cn];  // q, [n][c] bf16 transposed
__device__ __nv_bfloat16 g_kh[(size_t)NTOT*Cn];  // k, [n][c] bf16 transposed
__device__ float g_part[NTOT*NH];
__device__ float g_seeds[Bn*Cn];
__device__ float g_corr[NTOT];
__device__ float g_cormap[NTOT];
__device__ float g_proto[Cn];

__device__ __forceinline__ void cp16(uint32_t dst, const void* src) {
    asm volatile("cp.async.cg.shared.global [%0], [%1], 16;\n"
                 :: "r"(dst), "l"(src));
}
__device__ __forceinline__ uint32_t tf32r(float x) {
    uint32_t u;
    asm("cvt.rna.tf32.f32 %0, %1;" : "=r"(u) : "f"(x));
    return u;
}

// ---------------------------------------------------------------
// Tensor-core conv GEMM core: K=32 chunks, 3-stage ring, single
// barrier per chunk, single-pass tf32 (R16-proven arithmetic).
// MODE 0: + residual -> Yp fp32 (x5new).
// MODE 1: -> Yh bf16, transposed [n][c] (q/k projections).
// ---------------------------------------------------------------
#define CKC   32
#define CLDW  36                        // floats per W smem row (32+4)
#define CLDX  136                       // floats per X smem row (128+8)
#define WSTG  (128 * CLDW)              // floats per W stage (4608)
#define XSTG  (CKC * CLDX)              // floats per X stage (4352)
#define CSMEM (3 * (WSTG + XSTG) * 4)   // 107520 B

template<int MODE>
__device__ __forceinline__ void conv_body(const float* __restrict__ Wm,
                                          const float* __restrict__ Xin,
                                          const float* __restrict__ bias,
                                          float* __restrict__ Yp,
                                          __nv_bfloat16* __restrict__ Yh)
{
    extern __shared__ __align__(16) float smf[];
    float* WsF = smf;               // 3 stages of [128][CLDW]
    float* XsF = smf + 3 * WSTG;    // 3 stages of [CKC][CLDX]

    const int t    = threadIdx.x;
    const int warp = t >> 5;
    const int lane = t & 31;
    const int wm   = (warp & 1) * 64;
    const int wn   = (warp >> 1) * 32;
    const int lr   = lane >> 2;
    const int lc   = lane & 3;
    const int N0   = blockIdx.x * 128;
    const int O0   = blockIdx.y * 128;

    uint32_t wo[4], xo[4];
    const float* wsp[4];
    const float* xsp[4];
    #pragma unroll
    for (int i = 0; i < 4; i++) {
        const int idx = t + i * 256;          // 0..1023
        const int wr = idx >> 3, wsg = idx & 7;
        wo[i]  = (uint32_t)(wr * CLDW + wsg * 4) * 4;
        wsp[i] = Wm + (size_t)(O0 + wr) * Cn + wsg * 4;
        const int xr = idx >> 5, xsg = idx & 31;
        const int col = N0 + xsg * 4;
        xo[i]  = (uint32_t)(xr * CLDX + xsg * 4) * 4;
        xsp[i] = Xin + (size_t)(col / HWn) * CMn + (size_t)xr * HWn + (col % HWn);
    }
    const uint32_t wB = (uint32_t)__cvta_generic_to_shared(WsF);
    const uint32_t xB = (uint32_t)__cvta_generic_to_shared(XsF);
    const uint32_t wStB = (uint32_t)(WSTG * 4);
    const uint32_t xStB = (uint32_t)(XSTG * 4);

    float d[4][4][4];
    #pragma unroll
    for (int mi = 0; mi < 4; mi++)
        #pragma unroll
        for (int ni = 0; ni < 4; ni++)
            #pragma unroll
            for (int r = 0; r < 4; r++) d[mi][ni][r] = 0.f;

    const int NCH = Cn / CKC;   // 16 chunks

    #pragma unroll
    for (int s = 0; s < 2; s++) {
        #pragma unroll
        for (int i = 0; i < 4; i++) {
            cp16(wB + s * wStB + wo[i], wsp[i] + s * CKC);
            cp16(xB + s * xStB + xo[i], xsp[i] + (size_t)s * CKC * HWn);
        }
        asm volatile("cp.async.commit_group;\n" ::: "memory");
    }

    for (int cc = 0; cc < NCH; cc++) {
        asm volatile("cp.async.wait_group 1;\n" ::: "memory");
        __syncthreads();
        if (cc + 2 < NCH) {
            const int j = cc + 2;
            const uint32_t ws = (j % 3) * wStB;
            const uint32_t xs = (j % 3) * xStB;
            #pragma unroll
            for (int i = 0; i < 4; i++) {
                cp16(wB + ws + wo[i], wsp[i] + j * CKC);
                cp16(xB + xs + xo[i], xsp[i] + (size_t)j * CKC * HWn);
            }
        }
        asm volatile("cp.async.commit_group;\n" ::: "memory");

        const float* Wst = WsF + (cc % 3) * WSTG;
        const float* Xst = XsF + (cc % 3) * XSTG;
        #pragma unroll
        for (int kf = 0; kf < 4; kf++) {
            const int k0 = kf * 8;
            uint32_t ah[4][4];
            #pragma unroll
            for (int mi = 0; mi < 4; mi++) {
                ah[mi][0] = tf32r(Wst[(wm + mi * 16 + lr    ) * CLDW + k0 + lc    ]);
                ah[mi][1] = tf32r(Wst[(wm + mi * 16 + 8 + lr) * CLDW + k0 + lc    ]);
                ah[mi][2] = tf32r(Wst[(wm + mi * 16 + lr    ) * CLDW + k0 + lc + 4]);
                ah[mi][3] = tf32r(Wst[(wm + mi * 16 + 8 + lr) * CLDW + k0 + lc + 4]);
            }
            #pragma unroll
            for (int ni = 0; ni < 4; ni++) {
                uint32_t bh0 = tf32r(Xst[(k0 + lc    ) * CLDX + wn + ni * 8 + lr]);
                uint32_t bh1 = tf32r(Xst[(k0 + lc + 4) * CLDX + wn + ni * 8 + lr]);
                #pragma unroll
                for (int mi = 0; mi < 4; mi++)
                    asm volatile(
                        "mma.sync.aligned.m16n8k8.row.col.f32.tf32.tf32.f32 "
                        "{%0,%1,%2,%3}, {%4,%5,%6,%7}, {%8,%9}, {%0,%1,%2,%3};"
                        : "+f"(d[mi][ni][0]), "+f"(d[mi][ni][1]),
                          "+f"(d[mi][ni][2]), "+f"(d[mi][ni][3])
                        : "r"(ah[mi][0]), "r"(ah[mi][1]), "r"(ah[mi][2]), "r"(ah[mi][3]),
                          "r"(bh0), "r"(bh1));
            }
        }
        __syncthreads();
    }

    #pragma unroll
    for (int mi = 0; mi < 4; mi++) {
        const int row0 = O0 + wm + mi * 16 + lr;
        const float b0 = bias[row0];
        const float b1 = bias[row0 + 8];
        #pragma unroll
        for (int ni = 0; ni < 4; ni++) {
            const int col = N0 + wn + ni * 8 + 2 * lc;
            if (MODE == 0) {
                const int bb = col / HWn;
                const int m  = col - bb * HWn;
                float2 v0, v1;
                v0.x = d[mi][ni][0] + b0; v0.y = d[mi][ni][1] + b0;
                v1.x = d[mi][ni][2] + b1; v1.y = d[mi][ni][3] + b1;
                const float* x0 = Xin + (size_t)bb * CMn + (size_t)row0 * HWn + m;
                float2 r0 = *(const float2*)x0;
                float2 r1 = *(const float2*)(x0 + 8 * HWn);
                v0.x += r0.x; v0.y += r0.y;
                v1.x += r1.x; v1.y += r1.y;
                float* y0 = Yp + (size_t)bb * CMn + (size_t)row0 * HWn + m;
                *(float2*)y0 = v0;
                *(float2*)(y0 + 8 * HWn) = v1;
            } else {
                Yh[(size_t)col       * Cn + row0    ] = __float2bfloat16(d[mi][ni][0] + b0);
                Yh[(size_t)(col + 1) * Cn + row0    ] = __float2bfloat16(d[mi][ni][1] + b0);
                Yh[(size_t)col       * Cn + row0 + 8] = __float2bfloat16(d[mi][ni][2] + b1);
                Yh[(size_t)(col + 1) * Cn + row0 + 8] = __float2bfloat16(d[mi][ni][3] + b1);
            }
        }
    }
}

__global__ void __launch_bounds__(256) conv_x5k(const float* __restrict__ Wm,
                                                const float* __restrict__ Xin,
                                                const float* __restrict__ bias,
                                                float* __restrict__ Yp)
{
    conv_body<0>(Wm, Xin, bias, Yp, nullptr);
}

// merged q+k projections: blockIdx.z selects weights/bias/output
__global__ void __launch_bounds__(256) conv_qk(const float* __restrict__ qw,
                                               const float* __restrict__ kw,
                                               const float* __restrict__ Xin,
                                               const float* __restrict__ qb,
                                               const float* __restrict__ kb)
{
    if (blockIdx.z == 0)
        conv_body<1>(qw, Xin, qb, nullptr, g_qh);
    else
        conv_body<1>(kw, Xin, kb, nullptr, g_kh);
}

// ---------------------------------------------------------------
// bf16 scores GEMM v4 (proven, verbatim) — clock control.
// ---------------------------------------------------------------
#define KC4    64
#define LDQ4   72
#define TIL4   (128 * LDQ4 * 2)         // 18432 B per tile-stage
#define SMEMB4 (6 * TIL4)               // 110592 B

__global__ void __launch_bounds__(256) scores_bf4()
{
    extern __shared__ __align__(16) char sm[];
    __nv_bfloat16* Qb0 = (__nv_bfloat16*)sm;
    __nv_bfloat16* Kb0 = (__nv_bfloat16*)(sm + 3 * TIL4);
    float (*red)[4] = (float(*)[4])sm;

    const int t    = threadIdx.x;
    const int warp = t >> 5;
    const int lane = t & 31;
    const int wm   = (warp & 1) * 64;
    const int wn   = (warp >> 1) * 32;
    const int lr   = lane >> 2;
    const int lc   = lane & 3;
    const int R0   = blockIdx.x * 128;
    const int N0   = blockIdx.y * 128;

    uint32_t soff[4];
    const __nv_bfloat16* qsp[4];
    const __nv_bfloat16* ksp[4];
    #pragma unroll
    for (int i = 0; i < 4; i++) {
        const int idx = t + i * 256;
        const int row = idx >> 3;
        const int seg = idx & 7;
        soff[i] = row * (LDQ4 * 2) + seg * 16;
        qsp[i]  = g_qh + (size_t)(R0 + row) * Cn + seg * 8;
        ksp[i]  = g_kh + (size_t)(N0 + row) * Cn + seg * 8;
    }
    const uint32_t qB = (uint32_t)__cvta_generic_to_shared(Qb0);
    const uint32_t kB = (uint32_t)__cvta_generic_to_shared(Kb0);

    const int lrow = lane & 15;
    const int loff = (lane >> 4) * 16;
    const uint32_t qa0 = qB + (wm + lrow) * (LDQ4 * 2) + loff;
    const uint32_t ka0 = kB + (wn + lrow) * (LDQ4 * 2) + loff;

    float d[4][4][4];
    #pragma unroll
    for (int mi = 0; mi < 4; mi++)
        #pragma unroll
        for (int ni = 0; ni < 4; ni++)
            #pragma unroll
            for (int r = 0; r < 4; r++) d[mi][ni][r] = 0.f;

    const int NCH = Cn / KC4;

    #pragma unroll
    for (int s = 0; s < 2; s++) {
        #pragma unroll
        for (int i = 0; i < 4; i++) {
            cp16(qB + s * TIL4 + soff[i], qsp[i] + s * KC4);
            cp16(kB + s * TIL4 + soff[i], ksp[i] + s * KC4);
        }
        asm volatile("cp.async.commit_group;\n" ::: "memory");
    }

    #pragma unroll
    for (int cc = 0; cc < NCH; cc++) {
        asm volatile("cp.async.wait_group 1;\n" ::: "memory");
        __syncthreads();
        if (cc + 2 < NCH) {
            const uint32_t so = ((cc + 2) % 3) * TIL4;
            const int go = (cc + 2) * KC4;
            #pragma unroll
            for (int i = 0; i < 4; i++) {
                cp16(qB + so + soff[i], qsp[i] + go);
                cp16(kB + so + soff[i], ksp[i] + go);
            }
        }
        asm volatile("cp.async.commit_group;\n" ::: "memory");

        const uint32_t stO = (cc % 3) * TIL4;
        #pragma unroll
        for (int kf = 0; kf < 4; kf++) {
            const uint32_t ko = kf * 32;
            uint32_t a[4][4];
            #pragma unroll
            for (int mi = 0; mi < 4; mi++)
                asm volatile(
                    "ldmatrix.sync.aligned.m8n8.x4.shared.b16 {%0,%1,%2,%3}, [%4];"
                    : "=r"(a[mi][0]), "=r"(a[mi][1]), "=r"(a[mi][2]), "=r"(a[mi][3])
                    : "r"(qa0 + stO + ko + mi * 16 * (LDQ4 * 2)));
            uint32_t b[4][2];
            #pragma unroll
            for (int nj = 0; nj < 2; nj++)
                asm volatile(
                    "ldmatrix.sync.aligned.m8n8.x4.shared.b16 {%0,%1,%2,%3}, [%4];"
                    : "=r"(b[nj*2][0]), "=r"(b[nj*2+1][0]),
                      "=r"(b[nj*2][1]), "=r"(b[nj*2+1][1])
                    : "r"(ka0 + stO + ko + nj * 16 * (LDQ4 * 2)));
            #pragma unroll
            for (int mi = 0; mi < 4; mi++)
                #pragma unroll
                for (int ni = 0; ni < 4; ni++)
                    asm volatile(
                        "mma.sync.aligned.m16n8k16.row.col.f32.bf16.bf16.f32 "
                        "{%0,%1,%2,%3}, {%4,%5,%6,%7}, {%8,%9}, {%0,%1,%2,%3};"
                        : "+f"(d[mi][ni][0]), "+f"(d[mi][ni][1]),
                          "+f"(d[mi][ni][2]), "+f"(d[mi][ni][3])
                        : "r"(a[mi][0]), "r"(a[mi][1]), "r"(a[mi][2]), "r"(a[mi][3]),
                          "r"(b[ni][0]), "r"(b[ni][1]));
        }
    }
    __syncthreads();

    #pragma unroll
    for (int mi = 0; mi < 4; mi++) {
        float ra = -1e30f, rb = -1e30f;
        #pragma unroll
        for (int ni = 0; ni < 4; ni++) {
            ra = fmaxf(ra, fmaxf(d[mi][ni][0], d[mi][ni][1]));
            rb = fmaxf(rb, fmaxf(d[mi][ni][2], d[mi][ni][3]));
        }
        ra = fmaxf(ra, __shfl_xor_sync(0xFFFFFFFFu, ra, 1));
        ra = fmaxf(ra, __shfl_xor_sync(0xFFFFFFFFu, ra, 2));
        rb = fmaxf(rb, __shfl_xor_sync(0xFFFFFFFFu, rb, 1));
        rb = fmaxf(rb, __shfl_xor_sync(0xFFFFFFFFu, rb, 2));
        if (lc == 0) {
            red[wm + mi * 16 + lr    ][warp >> 1] = ra;
            red[wm + mi * 16 + 8 + lr][warp >> 1] = rb;
        }
    }
    __syncthreads();

    if (t < 128) {
        const float h0 = fmaxf(red[t][0], red[t][1]);
        const float h1 = fmaxf(red[t][2], red[t][3]);
        const size_t r2 = R0 + t;
        g_part[r2 * NH + blockIdx.y * 2    ] = h0;
        g_part[r2 * NH + blockIdx.y * 2 + 1] = h1;
    }
}

// ---------------------------------------------------------------
// fused x_w mask + seeds: one block per image, 576 threads.
// Phase 1: mask (identical math). Phase 2: seeds with inline norm
// (identical math; threads >= 512 only participate in barriers).
// ---------------------------------------------------------------
__global__ void __launch_bounds__(HWn) xw_seeds(const float* __restrict__ x5n,
                                                float* __restrict__ o_mask)
{
    __shared__ float smax[HWn];
    __shared__ int   cnt;
    __shared__ int   plist[HWn];
    __shared__ float red[512];

    const int b = blockIdx.x, p = threadIdx.x;
    const float* gp = g_part + (size_t)(b * HWn + p) * NH;
    float s = 0.f;
    #pragma unroll
    for (int bk = 0; bk < Bn; bk++) {
        float m = gp[bk * 9];
        #pragma unroll
        for (int h = 1; h < 9; h++) m = fmaxf(m, gp[bk * 9 + h]);
        s += m;
    }
    smax[p] = s;
    if (p == 0) cnt = 0;
    __syncthreads();
    for (int st = 512; st > 0; st >>= 1) {
        if (p < st && p + st < HWn) smax[p] = fmaxf(smax[p], smax[p + st]);
        __syncthreads();
    }
    const float mk = (s == smax[0]) ? 1.0f : 0.0f;
    o_mask[b * HWn + p] = mk;
    if (mk > 0.5f) {
        int i = atomicAdd(&cnt, 1);
        plist[i] = p;
    }
    __syncthreads();

    // seeds: thread c (< 512) accumulates over masked positions
    const int c = p;
    float acc = 0.f;
    const int n = cnt;
    for (int i = 0; i < n; i++) {
        const int pp = plist[i];
        float x = 0.f;
        if (c < Cn) {
            x = x5n[(size_t)b * CMn + (size_t)c * HWn + pp];
            red[c] = x * x;
        }
        __syncthreads();
        for (int st = 256; st > 0; st >>= 1) {
            if (c < st) red[c] += red[c + st];
            __syncthreads();
        }
        const float invn = 1.0f / fmaxf(sqrtf(red[0]), 1e-12f);
        if (c < Cn) acc += x * invn;
        __syncthreads();
    }
    if (c < Cn) g_seeds[b * Cn + c] = acc;
}

// corr with inline channel norm, 144 blocks x 64 threads -> g_corr
__global__ void __launch_bounds__(64) corr_k(const float* __restrict__ x5n)
{
    __shared__ __align__(16) float ssT[Cn][Bn];
    const int b = blockIdx.x;
    const int p = blockIdx.y * 64 + threadIdx.x;
    for (int i = threadIdx.x; i < Cn * Bn; i += 64) {
        int c = i >> 4, s = i & 15;
        ssT[c][s] = g_seeds[s * Cn + c];
    }
    __syncthreads();
    float acc[Bn] = {};
    float sq = 0.f;
    const float* xp = x5n + (size_t)b * CMn + p;
    for (int c = 0; c < Cn; c++) {
        const float x = xp[(size_t)c * HWn];
        sq += x * x;
        #pragma unroll
        for (int s4 = 0; s4 < 4; s4++) {
            float4 sv = *(const float4*)&ssT[c][s4 * 4];
            acc[s4 * 4 + 0] += x * sv.x;
            acc[s4 * 4 + 1] += x * sv.y;
            acc[s4 * 4 + 2] += x * sv.z;
            acc[s4 * 4 + 3] += x * sv.w;
        }
    }
    const float invn = 1.0f / fmaxf(sqrtf(sq), 1e-12f);
    float r = 0.f;
    #pragma unroll
    for (int s = 0; s < Bn; s++) r += fmaxf(acc[s], 0.f);
    g_corr[b * HWn + p] = r * invn * (1.0f / Bn);
}

__global__ void cormap_k()
{
    __shared__ float smn[HWn], smx[HWn];
    const int b = blockIdx.x, p = threadIdx.x;
    const float v = g_corr[b * HWn + p];
    smn[p] = v; smx[p] = v;
    __syncthreads();
    for (int st = 512; st > 0; st >>= 1) {
        if (p < st && p + st < HWn) {
            smn[p] = fminf(smn[p], smn[p + st]);
            smx[p] = fmaxf(smx[p], smx[p + st]);
        }
        __syncthreads();
    }
    g_cormap[b * HWn + p] = (v - smn[0]) / (smx[0] - smn[0] + 1e-12f);
}

__global__ void proto_kernel(const float* __restrict__ x5n,
                             float* __restrict__ o_pro)
{
    __shared__ float sred[256];
    const int c = blockIdx.x, t = threadIdx.x;
    float s = 0.f;
    for (int n = t; n < NTOT; n += 256) {
        int b = n / HWn, p = n - b * HWn;
        s += x5n[(size_t)b * CMn + (size_t)c * HWn + p] * g_cormap[n];
    }
    sred[t] = s;
    __syncthreads();
    for (int st = 128; st > 0; st >>= 1) {
        if (t < st) sred[t] += sred[t + st];
        __syncthreads();
    }
    if (t == 0) {
        float v = sred[0] * (1.0f / NTOT);
        g_proto[c] = v;
        o_pro[c] = v;
    }
}

// out3 vectorized: 4 consecutive elems share (b, c), cormap aligned
__global__ void out3_kernel(const float* __restrict__ x5n,
                            float* __restrict__ o3)
{
    const int i4 = (blockIdx.x * 256 + threadIdx.x) * 4;
    const int b = i4 / CMn;
    const int r = i4 - b * CMn;
    const int c = r / HWn;
    const int p = r - c * HWn;
    const float pr = g_proto[c];
    float4 x = *(const float4*)(x5n + i4);
    float4 cm = *(const float4*)(g_cormap + b * HWn + p);
    float4 o;
    o.x = x.x * (pr + cm.x);
    o.y = x.y * (pr + cm.y);
    o.z = x.z * (pr + cm.z);
    o.w = x.w * (pr + cm.w);
    *(float4*)(o3 + i4) = o;
}

// ---------------------------------------------------------------
extern "C" void kernel_launch(void* const* d_in, const int* in_sizes, int n_in,
                              void* d_out, int out_size)
{
    const float* x5    = (const float*)d_in[0];
    const float* convw = (const float*)d_in[1];
    const float* convb = (const float*)d_in[2];
    const float* qw    = (const float*)d_in[3];
    const float* qb    = (const float*)d_in[4];
    const float* kw    = (const float*)d_in[5];
    const float* kb    = (const float*)d_in[6];

    float* out    = (float*)d_out;
    float* o_x5   = out;
    float* o_pro  = out + (size_t)Bn * CMn;
    float* o_3    = o_pro + Cn;
    float* o_mask = o_3 + (size_t)Bn * CMn;

    static bool attr_set = false;
    if (!attr_set) {
        cudaFuncSetAttribute(scores_bf4,
                             cudaFuncAttributeMaxDynamicSharedMemorySize, SMEMB4);
        cudaFuncSetAttribute(conv_x5k,
                             cudaFuncAttributeMaxDynamicSharedMemorySize, CSMEM);
        cudaFuncSetAttribute(conv_qk,
                             cudaFuncAttributeMaxDynamicSharedMemorySize, CSMEM);
        attr_set = true;
    }

    dim3 cgrid(NTOT / 128, Cn / 128);          // (72, 4)
    dim3 qkgrid(NTOT / 128, Cn / 128, 2);      // (72, 4, 2)

    conv_x5k<<<cgrid, 256, CSMEM>>>(convw, x5, convb, o_x5);
    conv_qk<<<qkgrid, 256, CSMEM>>>(qw, kw, o_x5, qb, kb);

    scores_bf4<<<dim3(NTOT / 128, NTOT / 128), 256, SMEMB4>>>();

    xw_seeds<<<Bn, HWn>>>(o_x5, o_mask);
    corr_k<<<dim3(Bn, 9), 64>>>(o_x5);
    cormap_k<<<Bn, HWn>>>();
    proto_kernel<<<Cn, 256>>>(o_x5, o_pro);
    out3_kernel<<<(Bn * CMn) / 1024, 256>>>(o_x5, o_3);
}